// round 1
// baseline (speedup 1.0000x reference)
#include <cuda_runtime.h>

// ---------------------------------------------------------------------------
// RealVirtualAttention:
//   1) masked segment-mean over sorted batch (real vs virtual nodes) -> [B,2,D]
//   2) HAN semantic attention: score_m = sum_b q^T tanh(W1^T x_{b,m} + b1)
//      beta = softmax(score / B)
//   3) out[b] = beta0 * mean_real[b] + beta1 * mean_virtual[b]
// ---------------------------------------------------------------------------

#define VIRTUAL_Z 100LL
#define MAXB 8192
#define MAXD 256
#define GPB  8            // graphs per block in score kernel
#define VPB  (2*GPB)      // vectors per block (graphs x 2 metapaths)

__device__ float g_means[(size_t)MAXB * 2 * MAXD];   // [B][2][D] means
__device__ float g_part[(MAXB / GPB) * 2 + 2];       // per-block partial scores
__device__ float g_score[2];
__device__ int   g_is64;

// ---------------------------------------------------------------------------
// Detect whether z/batch are int64 or int32 (jax silently downcasts int64 ->
// int32 when x64 is disabled). batch is sorted, values in [0, B). Viewing the
// buffer as int32: if the true dtype is int64, odd positions are high words
// (== 0); if int32, odd positions near the end are ~B-1 (nonzero for B > 1).
// Only reads within the first N int32 slots -> in-bounds for both dtypes.
// ---------------------------------------------------------------------------
__global__ void init_kernel(const int* __restrict__ batch32, int N) {
    if (blockIdx.x == 0 && threadIdx.x == 0) {
        int is64 = 1;
        int idx = N - 1;
        if ((idx & 1) == 0) idx--;
        for (int k = 0; k < 8 && idx >= 1; k++, idx -= 2) {
            if (batch32[idx] != 0) { is64 = 0; break; }
        }
        g_is64 = is64;
        g_score[0] = 0.f;
        g_score[1] = 0.f;
    }
}

__device__ __forceinline__ long long idx_at(const void* p, int i, int is64) {
    return is64 ? ((const long long*)p)[i] : (long long)((const int*)p)[i];
}

__device__ __forceinline__ int lower_bound_idx(const void* p, int n,
                                               long long key, int is64) {
    int lo = 0, hi = n;
    while (lo < hi) {
        int mid = (lo + hi) >> 1;
        if (idx_at(p, mid, is64) < key) lo = mid + 1; else hi = mid;
    }
    return lo;
}

// ---------------------------------------------------------------------------
// Kernel 1: one block per graph. Binary-search the contiguous node range in
// the sorted batch array, accumulate real/virtual feature sums in registers
// (thread t owns feature d = t), write means to g_means.
// Dominant cost: streaming N*D*4 bytes (~600 MB) from HBM.
// ---------------------------------------------------------------------------
__global__ void seg_mean_kernel(const float* __restrict__ x,
                                const void*  __restrict__ z,
                                const void*  __restrict__ batch,
                                int N, int D) {
    const int b = blockIdx.x;
    const int is64 = g_is64;
    const int start = lower_bound_idx(batch, N, (long long)b, is64);
    const int end   = lower_bound_idx(batch, N, (long long)b + 1, is64);
    const int t = threadIdx.x;

    float sr = 0.f, sv = 0.f;
    int   cr = 0,   cv = 0;

    #pragma unroll 4
    for (int i = start; i < end; i++) {
        const long long zi = idx_at(z, i, is64);
        const bool real = (zi != VIRTUAL_Z);
        float v = 0.f;
        if (t < D) v = x[(size_t)i * D + t];
        if (real) { sr += v; cr++; } else { sv += v; cv++; }
    }

    if (t < D) {
        float* mr = g_means + (size_t)b * 2 * D;
        mr[t]     = sr / (float)max(cr, 1);
        mr[D + t] = sv / (float)max(cv, 1);
    }
}

// ---------------------------------------------------------------------------
// Kernel 2: semantic attention scores. Each block handles GPB graphs
// (VPB = 16 vectors). x-vectors live in SMEM padded to a multiple of 4
// floats (float4 broadcasts); W1 is read from global and stays L1-resident
// (76.8 KB, shared by all blocks on the SM). Per-block partial score sums
// are written without atomics for determinism.
// ---------------------------------------------------------------------------
__global__ void score_kernel(const float* __restrict__ W1,
                             const float* __restrict__ b1,
                             const float* __restrict__ q,
                             int D, int Dp, int A, int B) {
    extern __shared__ float sx[];   // [VPB][Dp]
    const int b0 = blockIdx.x * GPB;
    const int nv = min(VPB, 2 * (B - b0));   // valid vectors in this block

    // Stage x vectors into shared memory (zero padding)
    for (int i = threadIdx.x; i < VPB * Dp; i += blockDim.x) {
        const int v = i / Dp;
        const int d = i - v * Dp;
        float val = 0.f;
        if (v < nv && d < D) val = g_means[((size_t)b0 * 2 + v) * D + d];
        sx[i] = val;
    }
    __syncthreads();

    float t0 = 0.f, t1 = 0.f;
    for (int aa = threadIdx.x; aa < A; aa += blockDim.x) {
        float acc[VPB];
        const float bb = b1[aa];
        #pragma unroll
        for (int v = 0; v < VPB; v++) acc[v] = bb;

        for (int d = 0; d < Dp; d += 4) {
            const float w0 = (d + 0 < D) ? W1[(size_t)(d + 0) * A + aa] : 0.f;
            const float w1 = (d + 1 < D) ? W1[(size_t)(d + 1) * A + aa] : 0.f;
            const float w2 = (d + 2 < D) ? W1[(size_t)(d + 2) * A + aa] : 0.f;
            const float w3 = (d + 3 < D) ? W1[(size_t)(d + 3) * A + aa] : 0.f;
            #pragma unroll
            for (int v = 0; v < VPB; v++) {
                const float4 xv = *reinterpret_cast<const float4*>(&sx[v * Dp + d]);
                acc[v] = fmaf(xv.x, w0, acc[v]);
                acc[v] = fmaf(xv.y, w1, acc[v]);
                acc[v] = fmaf(xv.z, w2, acc[v]);
                acc[v] = fmaf(xv.w, w3, acc[v]);
            }
        }

        const float qa = q[aa];
        #pragma unroll
        for (int v = 0; v < VPB; v++) {
            if (v < nv) {
                const float tv = tanhf(acc[v]) * qa;
                if (v & 1) t1 += tv; else t0 += tv;
            }
        }
    }

    // Block reduction (fixed order -> deterministic)
    #pragma unroll
    for (int off = 16; off; off >>= 1) {
        t0 += __shfl_down_sync(0xffffffffu, t0, off);
        t1 += __shfl_down_sync(0xffffffffu, t1, off);
    }
    __shared__ float r0[32], r1[32];
    const int w = threadIdx.x >> 5;
    if ((threadIdx.x & 31) == 0) { r0[w] = t0; r1[w] = t1; }
    __syncthreads();
    if (threadIdx.x == 0) {
        float s0 = 0.f, s1 = 0.f;
        const int nw = (blockDim.x + 31) >> 5;
        for (int i = 0; i < nw; i++) { s0 += r0[i]; s1 += r1[i]; }
        g_part[2 * blockIdx.x + 0] = s0;
        g_part[2 * blockIdx.x + 1] = s1;
    }
}

// ---------------------------------------------------------------------------
// Kernel 3: deterministic reduction of per-block partials into g_score.
// ---------------------------------------------------------------------------
__global__ void reduce_kernel(int nblk) {
    __shared__ float sh0[256], sh1[256];
    const int t = threadIdx.x;
    float s0 = 0.f, s1 = 0.f;
    for (int i = t; i < nblk; i += 256) {
        s0 += g_part[2 * i + 0];
        s1 += g_part[2 * i + 1];
    }
    sh0[t] = s0; sh1[t] = s1;
    __syncthreads();
    for (int o = 128; o; o >>= 1) {
        if (t < o) { sh0[t] += sh0[t + o]; sh1[t] += sh1[t + o]; }
        __syncthreads();
    }
    if (t == 0) { g_score[0] = sh0[0]; g_score[1] = sh1[0]; }
}

// ---------------------------------------------------------------------------
// Kernel 4: beta = softmax(score / B); out[b,d] = beta0*mean_r + beta1*mean_v
// ---------------------------------------------------------------------------
__global__ void combine_kernel(float* __restrict__ outp, int B, int D) {
    const float invB = 1.f / (float)B;
    const float s0 = g_score[0] * invB;
    const float s1 = g_score[1] * invB;
    const float mx = fmaxf(s0, s1);
    const float e0 = expf(s0 - mx);
    const float e1 = expf(s1 - mx);
    const float beta0 = e0 / (e0 + e1);
    const float beta1 = 1.f - beta0;

    const int idx = blockIdx.x * blockDim.x + threadIdx.x;
    const int tot = B * D;
    if (idx < tot) {
        const int b = idx / D;
        const int d = idx - b * D;
        const float* mr = g_means + (size_t)b * 2 * D;
        outp[idx] = mr[d] * beta0 + mr[D + d] * beta1;
    }
}

// ---------------------------------------------------------------------------
extern "C" void kernel_launch(void* const* d_in, const int* in_sizes, int n_in,
                              void* d_out, int out_size) {
    const float* x   = (const float*)d_in[0];   // out [N, D] fp32
    const void*  z   = d_in[1];                 // z   [N] int32/int64
    const void*  bat = d_in[2];                 // batch [N] sorted int32/int64
    const float* W1  = (const float*)d_in[3];   // [D, A]
    const float* b1  = (const float*)d_in[4];   // [A]
    const float* q   = (const float*)d_in[5];   // [A, 1]
    // d_in[6] (num_graphs) unused: B derived from out_size

    const int N = in_sizes[1];
    const int D = in_sizes[0] / N;
    const int A = in_sizes[4];
    const int B = out_size / D;

    init_kernel<<<1, 32>>>((const int*)bat, N);

    int tpb1 = ((D + 31) / 32) * 32;
    if (tpb1 < 32) tpb1 = 32;
    if (tpb1 > 1024) tpb1 = 1024;
    seg_mean_kernel<<<B, tpb1>>>(x, z, bat, N, D);

    const int Dp = (D + 3) & ~3;
    int tpb2 = (A < 256) ? ((A + 31) / 32) * 32 : 256;
    if (tpb2 < 32) tpb2 = 32;
    const int nblk2 = (B + GPB - 1) / GPB;
    const size_t shmem = (size_t)VPB * Dp * sizeof(float);
    score_kernel<<<nblk2, tpb2, shmem>>>(W1, b1, q, D, Dp, A, B);

    reduce_kernel<<<1, 256>>>(nblk2);

    const int tot = B * D;
    combine_kernel<<<(tot + 255) / 256, 256>>>((float*)d_out, B, D);
}

// round 2
// speedup vs baseline: 1.2379x; 1.2379x over previous
#include <cuda_runtime.h>

// ---------------------------------------------------------------------------
// RealVirtualAttention:
//   1) masked segment-mean over sorted batch (real vs virtual nodes) -> [B,2,D]
//   2) HAN semantic attention: score_m = sum_b q^T tanh(W1^T x_{b,m} + b1)
//      beta = softmax(score / B)
//   3) out[b] = beta0 * mean_real[b] + beta1 * mean_virtual[b]
// ---------------------------------------------------------------------------

#define VIRTUAL_Z 100
#define MAXB 8192
#define MAXD 256
#define GPB  8            // graphs per block in score kernel
#define VPB  (2*GPB)      // vectors per block (graphs x 2 metapaths)

__device__ float g_means[(size_t)MAXB * 2 * MAXD];   // [B][2][D] means
__device__ float g_part[(MAXB / GPB) * 2 + 2];       // per-block partial scores
__device__ float g_score[2];
__device__ int   g_is64;
__device__ int   g_bounds[MAXB + 1];                 // row range per graph

// ---------------------------------------------------------------------------
// Detect whether z/batch are int64 or int32 (jax silently downcasts int64 ->
// int32 when x64 is disabled). batch is sorted, values in [0, B). Viewing the
// buffer as int32: if true dtype is int64, odd positions are high words (0);
// if int32, odd positions near the end are ~B-1 (nonzero for B > 1).
// ---------------------------------------------------------------------------
__global__ void init_kernel(const int* __restrict__ batch32, int N) {
    if (threadIdx.x == 0) {
        int is64 = 1;
        int idx = N - 1;
        if ((idx & 1) == 0) idx--;
        for (int k = 0; k < 8 && idx >= 1; k++, idx -= 2) {
            if (batch32[idx] != 0) { is64 = 0; break; }
        }
        g_is64 = is64;
        g_score[0] = 0.f;
        g_score[1] = 0.f;
    }
}

// ---------------------------------------------------------------------------
// Boundary kernel: g_bounds[b] = first row index with batch >= b.
// Single pass over batch (sorted). Low 32-bit word works for both dtypes.
// ---------------------------------------------------------------------------
__global__ void bounds_kernel(const int* __restrict__ bat32, int N, int B) {
    const int i = blockIdx.x * blockDim.x + threadIdx.x;
    if (i >= N) return;
    const int s = g_is64;
    const int cur  = bat32[(size_t)i << s];
    const int prev = (i == 0) ? -1 : bat32[(size_t)(i - 1) << s];
    for (int b = prev + 1; b <= cur; b++) g_bounds[b] = i;
    if (i == N - 1) {
        for (int b = cur + 1; b <= B; b++) g_bounds[b] = N;
    }
}

// ---------------------------------------------------------------------------
// Kernel 1 (hot): one block per graph, thread t owns feature pair (2t, 2t+1).
// 8-row software pipeline: batch all loads (8 z broadcasts + 8 float2) before
// accumulation -> MLP >= 8 per thread, float2 halves LDG count.
// Row stride D*4 bytes is 8-aligned for even D -> float2 is always legal.
// ---------------------------------------------------------------------------
__global__ void seg_mean_vec_kernel(const float* __restrict__ x,
                                    const int*   __restrict__ z32,
                                    int D) {
    const int b = blockIdx.x;
    const int s = g_is64;
    const int start = g_bounds[b];
    const int end   = g_bounds[b + 1];
    const int t  = threadIdx.x;
    const int D2 = D >> 1;
    const float2* __restrict__ x2 = reinterpret_cast<const float2*>(x);

    float2 sr = make_float2(0.f, 0.f);
    float2 sv = make_float2(0.f, 0.f);
    int cr = 0, cv = 0;

    int i = start;
    for (; i + 8 <= end; i += 8) {
        int zz[8];
        float2 v[8];
        #pragma unroll
        for (int k = 0; k < 8; k++) zz[k] = z32[(size_t)(i + k) << s];
        #pragma unroll
        for (int k = 0; k < 8; k++) {
            v[k] = (t < D2) ? __ldcs(&x2[(size_t)(i + k) * D2 + t])
                            : make_float2(0.f, 0.f);
        }
        #pragma unroll
        for (int k = 0; k < 8; k++) {
            if (zz[k] != VIRTUAL_Z) { sr.x += v[k].x; sr.y += v[k].y; cr++; }
            else                    { sv.x += v[k].x; sv.y += v[k].y; cv++; }
        }
    }
    for (; i < end; i++) {
        const int zz = z32[(size_t)i << s];
        float2 v = (t < D2) ? __ldcs(&x2[(size_t)i * D2 + t])
                            : make_float2(0.f, 0.f);
        if (zz != VIRTUAL_Z) { sr.x += v.x; sr.y += v.y; cr++; }
        else                 { sv.x += v.x; sv.y += v.y; cv++; }
    }

    if (t < D2) {
        const float ir = 1.f / (float)max(cr, 1);
        const float iv = 1.f / (float)max(cv, 1);
        float* mr = g_means + (size_t)b * 2 * D;
        reinterpret_cast<float2*>(mr)[t]     = make_float2(sr.x * ir, sr.y * ir);
        reinterpret_cast<float2*>(mr + D)[t] = make_float2(sv.x * iv, sv.y * iv);
    }
}

// Scalar fallback for odd D (not hit for this problem's shapes).
__global__ void seg_mean_scalar_kernel(const float* __restrict__ x,
                                       const int*   __restrict__ z32,
                                       int D) {
    const int b = blockIdx.x;
    const int s = g_is64;
    const int start = g_bounds[b];
    const int end   = g_bounds[b + 1];
    const int t = threadIdx.x;

    float sr = 0.f, sv = 0.f;
    int cr = 0, cv = 0;
    for (int i = start; i < end; i++) {
        const int zz = z32[(size_t)i << s];
        float v = (t < D) ? x[(size_t)i * D + t] : 0.f;
        if (zz != VIRTUAL_Z) { sr += v; cr++; } else { sv += v; cv++; }
    }
    if (t < D) {
        float* mr = g_means + (size_t)b * 2 * D;
        mr[t]     = sr / (float)max(cr, 1);
        mr[D + t] = sv / (float)max(cv, 1);
    }
}

// ---------------------------------------------------------------------------
// Kernel 2: semantic attention scores. Each block handles GPB graphs
// (VPB = 16 vectors). x-vectors live in SMEM padded to multiples of 4 floats;
// W1 stays L1/L2 resident (76.8 KB shared by all blocks). Per-block partial
// score sums written without atomics for determinism.
// ---------------------------------------------------------------------------
__global__ void score_kernel(const float* __restrict__ W1,
                             const float* __restrict__ b1,
                             const float* __restrict__ q,
                             int D, int Dp, int A, int B) {
    extern __shared__ float sx[];   // [VPB][Dp]
    const int b0 = blockIdx.x * GPB;
    const int nv = min(VPB, 2 * (B - b0));   // valid vectors in this block

    for (int i = threadIdx.x; i < VPB * Dp; i += blockDim.x) {
        const int v = i / Dp;
        const int d = i - v * Dp;
        float val = 0.f;
        if (v < nv && d < D) val = g_means[((size_t)b0 * 2 + v) * D + d];
        sx[i] = val;
    }
    __syncthreads();

    float t0 = 0.f, t1 = 0.f;
    for (int aa = threadIdx.x; aa < A; aa += blockDim.x) {
        float acc[VPB];
        const float bb = b1[aa];
        #pragma unroll
        for (int v = 0; v < VPB; v++) acc[v] = bb;

        for (int d = 0; d < Dp; d += 4) {
            const float w0 = (d + 0 < D) ? W1[(size_t)(d + 0) * A + aa] : 0.f;
            const float w1 = (d + 1 < D) ? W1[(size_t)(d + 1) * A + aa] : 0.f;
            const float w2 = (d + 2 < D) ? W1[(size_t)(d + 2) * A + aa] : 0.f;
            const float w3 = (d + 3 < D) ? W1[(size_t)(d + 3) * A + aa] : 0.f;
            #pragma unroll
            for (int v = 0; v < VPB; v++) {
                const float4 xv = *reinterpret_cast<const float4*>(&sx[v * Dp + d]);
                acc[v] = fmaf(xv.x, w0, acc[v]);
                acc[v] = fmaf(xv.y, w1, acc[v]);
                acc[v] = fmaf(xv.z, w2, acc[v]);
                acc[v] = fmaf(xv.w, w3, acc[v]);
            }
        }

        const float qa = q[aa];
        #pragma unroll
        for (int v = 0; v < VPB; v++) {
            if (v < nv) {
                const float tv = tanhf(acc[v]) * qa;
                if (v & 1) t1 += tv; else t0 += tv;
            }
        }
    }

    #pragma unroll
    for (int off = 16; off; off >>= 1) {
        t0 += __shfl_down_sync(0xffffffffu, t0, off);
        t1 += __shfl_down_sync(0xffffffffu, t1, off);
    }
    __shared__ float r0[32], r1[32];
    const int w = threadIdx.x >> 5;
    if ((threadIdx.x & 31) == 0) { r0[w] = t0; r1[w] = t1; }
    __syncthreads();
    if (threadIdx.x == 0) {
        float s0 = 0.f, s1 = 0.f;
        const int nw = (blockDim.x + 31) >> 5;
        for (int i = 0; i < nw; i++) { s0 += r0[i]; s1 += r1[i]; }
        g_part[2 * blockIdx.x + 0] = s0;
        g_part[2 * blockIdx.x + 1] = s1;
    }
}

// ---------------------------------------------------------------------------
// Kernel 3: deterministic reduction of per-block partials into g_score.
// ---------------------------------------------------------------------------
__global__ void reduce_kernel(int nblk) {
    __shared__ float sh0[128], sh1[128];
    const int t = threadIdx.x;
    float s0 = 0.f, s1 = 0.f;
    for (int i = t; i < nblk; i += 128) {
        s0 += g_part[2 * i + 0];
        s1 += g_part[2 * i + 1];
    }
    sh0[t] = s0; sh1[t] = s1;
    __syncthreads();
    for (int o = 64; o; o >>= 1) {
        if (t < o) { sh0[t] += sh0[t + o]; sh1[t] += sh1[t + o]; }
        __syncthreads();
    }
    if (t == 0) { g_score[0] = sh0[0]; g_score[1] = sh1[0]; }
}

// ---------------------------------------------------------------------------
// Kernel 4: beta = softmax(score / B); out[b,d] = beta0*mean_r + beta1*mean_v
// ---------------------------------------------------------------------------
__global__ void combine_kernel(float* __restrict__ outp, int B, int D) {
    const float invB = 1.f / (float)B;
    const float s0 = g_score[0] * invB;
    const float s1 = g_score[1] * invB;
    const float mx = fmaxf(s0, s1);
    const float e0 = expf(s0 - mx);
    const float e1 = expf(s1 - mx);
    const float beta0 = e0 / (e0 + e1);
    const float beta1 = 1.f - beta0;

    const int idx = blockIdx.x * blockDim.x + threadIdx.x;
    const int tot = B * D;
    if (idx < tot) {
        const int b = idx / D;
        const int d = idx - b * D;
        const float* mr = g_means + (size_t)b * 2 * D;
        outp[idx] = mr[d] * beta0 + mr[D + d] * beta1;
    }
}

// ---------------------------------------------------------------------------
extern "C" void kernel_launch(void* const* d_in, const int* in_sizes, int n_in,
                              void* d_out, int out_size) {
    const float* x   = (const float*)d_in[0];   // out [N, D] fp32
    const int*   z   = (const int*)d_in[1];     // z   [N] int32/int64
    const int*   bat = (const int*)d_in[2];     // batch [N] sorted int32/int64
    const float* W1  = (const float*)d_in[3];   // [D, A]
    const float* b1  = (const float*)d_in[4];   // [A]
    const float* q   = (const float*)d_in[5];   // [A, 1]

    const int N = in_sizes[1];
    const int D = in_sizes[0] / N;
    const int A = in_sizes[4];
    const int B = out_size / D;

    init_kernel<<<1, 32>>>(bat, N);

    bounds_kernel<<<(N + 255) / 256, 256>>>(bat, N, B);

    if ((D & 1) == 0) {
        const int D2 = D >> 1;
        int tpb = ((D2 + 31) / 32) * 32;
        if (tpb > 1024) tpb = 1024;
        seg_mean_vec_kernel<<<B, tpb>>>(x, z, D);
    } else {
        int tpb = ((D + 31) / 32) * 32;
        if (tpb > 1024) tpb = 1024;
        seg_mean_scalar_kernel<<<B, tpb>>>(x, z, D);
    }

    const int Dp = (D + 3) & ~3;
    int tpb2 = (A < 256) ? ((A + 31) / 32) * 32 : 256;
    if (tpb2 < 32) tpb2 = 32;
    const int nblk2 = (B + GPB - 1) / GPB;
    const size_t shmem = (size_t)VPB * Dp * sizeof(float);
    score_kernel<<<nblk2, tpb2, shmem>>>(W1, b1, q, D, Dp, A, B);

    reduce_kernel<<<1, 128>>>(nblk2);

    const int tot = B * D;
    combine_kernel<<<(tot + 255) / 256, 256>>>((float*)d_out, B, D);
}